// round 2
// baseline (speedup 1.0000x reference)
#include <cuda_runtime.h>
#include <cuda_bf16.h>
#include <cstdint>

// Problem constants (AttentionPool: N=262144, D=512, H=128, B=1024)
#define MAXN 262144
#define MAXB 4096
#define DIM 512
#define HID 128

// Scratch (allocation-free rule: __device__ globals)
__device__ float g_scores[MAXN];
__device__ float g_w[MAXN];
__device__ int   g_off[MAXB + 1];
__device__ int   g_batch_is_i32;

// ---------------------------------------------------------------------------
// Kernel 0: detect batch dtype. int32 layout: last element = max id > 0.
// int64 LE layout: i32 index n-1 (odd, n even) is a high word = 0.
// ---------------------------------------------------------------------------
__global__ void detect_batch_kernel(const int* __restrict__ batch_i32, int n)
{
    g_batch_is_i32 = (batch_i32[n - 1] != 0) ? 1 : 0;
}

// ---------------------------------------------------------------------------
// Kernel 0b: segment offsets via binary search over sorted batch ids.
// g_off[b] = first index with batch[i] >= b, for b in [0, Bseg].
// ---------------------------------------------------------------------------
__global__ void seg_offsets_kernel(const void* __restrict__ batch, int n, int Bseg)
{
    int b = blockIdx.x * blockDim.x + threadIdx.x;
    if (b > Bseg) return;
    const int i32 = g_batch_is_i32;
    int lo = 0, hi = n;
    if (i32) {
        const int* a = (const int*)batch;
        while (lo < hi) {
            int mid = (lo + hi) >> 1;
            if (__ldg(a + mid) < b) lo = mid + 1; else hi = mid;
        }
    } else {
        const long long* a = (const long long*)batch;
        while (lo < hi) {
            int mid = (lo + hi) >> 1;
            if (__ldg(a + mid) < (long long)b) lo = mid + 1; else hi = mid;
        }
    }
    g_off[b] = lo;
}

// ---------------------------------------------------------------------------
// Kernel 1: scores = tanh(x @ W1 + b1) @ W2 + b2     (written to g_scores)
// Tiled GEMM: 64 rows x 128 cols per block, fp32 with packed fma.rn.f32x2.
// ---------------------------------------------------------------------------
#define BR 64        // rows per block
#define KT 32        // k-tile
#define THREADS1 256

__global__ __launch_bounds__(THREADS1)
void score_kernel(const float* __restrict__ x,
                  const float* __restrict__ W1,
                  const float* __restrict__ b1,
                  const float* __restrict__ W2,
                  const float* __restrict__ b2,
                  int n)
{
    __shared__ float xs[BR][KT + 1];   // +1 pad: avoid bank conflicts on column reads
    __shared__ float ws[KT][HID];
    __shared__ float red[BR][17];      // row-partial reduction, padded

    const int tid = threadIdx.x;
    const int tx = tid & 15;           // 16 threads across columns
    const int ty = tid >> 4;           // 16 thread-groups across rows
    const int r0 = ty * 4;             // 4 rows per thread
    const int c0 = tx * 8;             // 8 cols per thread (4 x f32x2)
    const int rowBase = blockIdx.x * BR;

    unsigned long long acc[4][4];
#pragma unroll
    for (int i = 0; i < 4; i++)
#pragma unroll
        for (int j = 0; j < 4; j++) acc[i][j] = 0ull;

    for (int kt = 0; kt < DIM; kt += KT) {
        // stage X tile: 64x32 floats = 512 float4, 2 per thread
#pragma unroll
        for (int u = 0; u < 2; u++) {
            int idx = tid + u * 256;
            int r = idx >> 3;
            int c4 = (idx & 7) * 4;
            float4 v = *reinterpret_cast<const float4*>(
                x + (size_t)(rowBase + r) * DIM + kt + c4);
            xs[r][c4 + 0] = v.x; xs[r][c4 + 1] = v.y;
            xs[r][c4 + 2] = v.z; xs[r][c4 + 3] = v.w;
        }
        // stage W1 tile: 32x128 floats = 1024 float4, 4 per thread
#pragma unroll
        for (int u = 0; u < 4; u++) {
            int idx = tid + u * 256;
            int r = idx >> 5;
            int c4 = (idx & 31) * 4;
            *reinterpret_cast<float4*>(&ws[r][c4]) =
                *reinterpret_cast<const float4*>(W1 + (size_t)(kt + r) * HID + c4);
        }
        __syncthreads();

#pragma unroll
        for (int k = 0; k < KT; k++) {
            unsigned long long bv[4];
            const unsigned long long* wrow =
                reinterpret_cast<const unsigned long long*>(&ws[k][c0]);
#pragma unroll
            for (int j = 0; j < 4; j++) bv[j] = wrow[j];
#pragma unroll
            for (int i = 0; i < 4; i++) {
                unsigned int au = __float_as_uint(xs[r0 + i][k]);
                unsigned long long pa;
                asm("mov.b64 %0, {%1, %2};" : "=l"(pa) : "r"(au), "r"(au));
#pragma unroll
                for (int j = 0; j < 4; j++) {
                    asm("fma.rn.f32x2 %0, %1, %2, %0;"
                        : "+l"(acc[i][j]) : "l"(pa), "l"(bv[j]));
                }
            }
        }
        __syncthreads();
    }

    // Epilogue: tanh(h + b1) . W2 partial per (row, col-slice)
    float p[4] = {0.f, 0.f, 0.f, 0.f};
#pragma unroll
    for (int j = 0; j < 4; j++) {
        int c = c0 + j * 2;
        float b1a = __ldg(b1 + c),     b1b = __ldg(b1 + c + 1);
        float w2a = __ldg(W2 + c),     w2b = __ldg(W2 + c + 1);
#pragma unroll
        for (int i = 0; i < 4; i++) {
            unsigned int lo, hi;
            asm("mov.b64 {%0, %1}, %2;" : "=r"(lo), "=r"(hi) : "l"(acc[i][j]));
            p[i] += tanhf(__uint_as_float(lo) + b1a) * w2a
                  + tanhf(__uint_as_float(hi) + b1b) * w2b;
        }
    }
#pragma unroll
    for (int i = 0; i < 4; i++) red[r0 + i][tx] = p[i];
    __syncthreads();

    if (tid < BR) {
        float s = 0.f;
#pragma unroll
        for (int t = 0; t < 16; t++) s += red[tid][t];
        g_scores[rowBase + tid] = s + __ldg(b2);
    }
}

// ---------------------------------------------------------------------------
// Kernel 2: per-segment softmax weights -> g_w
// (Per-segment max-shift == reference's global max-shift: softmax is
//  shift-invariant; the +1e-8 denom term contributes ~1e-9 relative.)
// ---------------------------------------------------------------------------
__global__ __launch_bounds__(256)
void seg_softmax_kernel()
{
    const int b = blockIdx.x;
    const int tid = threadIdx.x;
    __shared__ float red[256];

    const int lo = g_off[b];
    const int hi = g_off[b + 1];

    // pass 1: segment max
    float m = -3.402823466e38f;
    for (int i = lo + tid; i < hi; i += 256) m = fmaxf(m, g_scores[i]);
    red[tid] = m;
    __syncthreads();
    for (int s = 128; s > 0; s >>= 1) {
        if (tid < s) red[tid] = fmaxf(red[tid], red[tid + s]);
        __syncthreads();
    }
    const float mm = red[0];
    __syncthreads();

    // pass 2: exp + sum
    float sum = 0.f;
    for (int i = lo + tid; i < hi; i += 256) {
        float e = expf(g_scores[i] - mm);
        g_w[i] = e;
        sum += e;
    }
    red[tid] = sum;
    __syncthreads();
    for (int s = 128; s > 0; s >>= 1) {
        if (tid < s) red[tid] += red[tid + s];
        __syncthreads();
    }
    const float inv = 1.f / (red[0] + 1e-8f);

    // pass 3: normalize
    for (int i = lo + tid; i < hi; i += 256) g_w[i] *= inv;
}

// ---------------------------------------------------------------------------
// Kernel 3: out[b, :] = sum_i w_i * x[i, :]   over segment rows
// 128 threads x float4 covers D=512.
// ---------------------------------------------------------------------------
__global__ __launch_bounds__(128)
void pool_kernel(const float* __restrict__ x, float* __restrict__ out)
{
    const int b = blockIdx.x;
    const int tid = threadIdx.x;

    const int lo = g_off[b];
    const int hi = g_off[b + 1];

    const float4* xv = reinterpret_cast<const float4*>(x) + tid;  // + i*128 per row
    float4 acc = make_float4(0.f, 0.f, 0.f, 0.f);

    int i = lo;
    for (; i + 4 <= hi; i += 4) {
        float w0 = __ldg(g_w + i + 0), w1 = __ldg(g_w + i + 1);
        float w2 = __ldg(g_w + i + 2), w3 = __ldg(g_w + i + 3);
        float4 v0 = __ldg(xv + (size_t)(i + 0) * (DIM / 4));
        float4 v1 = __ldg(xv + (size_t)(i + 1) * (DIM / 4));
        float4 v2 = __ldg(xv + (size_t)(i + 2) * (DIM / 4));
        float4 v3 = __ldg(xv + (size_t)(i + 3) * (DIM / 4));
        acc.x += w0 * v0.x + w1 * v1.x + w2 * v2.x + w3 * v3.x;
        acc.y += w0 * v0.y + w1 * v1.y + w2 * v2.y + w3 * v3.y;
        acc.z += w0 * v0.z + w1 * v1.z + w2 * v2.z + w3 * v3.z;
        acc.w += w0 * v0.w + w1 * v1.w + w2 * v2.w + w3 * v3.w;
    }
    for (; i < hi; i++) {
        float w = __ldg(g_w + i);
        float4 v = __ldg(xv + (size_t)i * (DIM / 4));
        acc.x += w * v.x; acc.y += w * v.y; acc.z += w * v.z; acc.w += w * v.w;
    }

    reinterpret_cast<float4*>(out)[(size_t)b * (DIM / 4) + tid] = acc;
}

// ---------------------------------------------------------------------------
extern "C" void kernel_launch(void* const* d_in, const int* in_sizes, int n_in,
                              void* d_out, int out_size)
{
    const float* x     = (const float*)d_in[0];
    const void*  batch = (const void*)d_in[1];
    const float* W1    = (const float*)d_in[2];
    const float* b1    = (const float*)d_in[3];
    const float* W2    = (const float*)d_in[4];
    const float* b2    = (const float*)d_in[5];
    float*       out   = (float*)d_out;

    const int n = in_sizes[1];          // N from batch element count
    const int Bseg = out_size / DIM;    // number of segments

    detect_batch_kernel<<<1, 1>>>((const int*)batch, n);
    seg_offsets_kernel<<<(Bseg + 256) / 256, 256>>>(batch, n, Bseg);
    score_kernel<<<n / BR, THREADS1>>>(x, W1, b1, W2, b2, n);
    seg_softmax_kernel<<<Bseg, 256>>>();
    pool_kernel<<<Bseg, 128>>>(x, out);
}

// round 4
// speedup vs baseline: 2.9741x; 2.9741x over previous
#include <cuda_runtime.h>
#include <cuda_bf16.h>
#include <cstdint>

// Problem constants (AttentionPool: N=262144, D=512, H=128, B=1024)
#define MAXN 262144
#define MAXB 4096
#define DIM 512
#define HID 128

// ---------------------------------------------------------------------------
// Scratch (allocation-free rule: __device__ globals)
// ---------------------------------------------------------------------------
__device__ float g_scores[MAXN];
__device__ float g_w[MAXN];
__device__ int   g_off[MAXB + 1];
__device__ int   g_batch_is_i32;
// W1^T split into bf16 hi/lo, layout [n][k]: n=0..127 rows, k=0..511 contiguous
__device__ __align__(16) unsigned short g_w1t_hi[HID * DIM];
__device__ __align__(16) unsigned short g_w1t_lo[HID * DIM];

// ---------------------------------------------------------------------------
// Kernel 0: detect batch dtype. int32: last element = max id > 0.
// int64 LE: i32 word at index n-1 (odd) is a high word = 0.
// ---------------------------------------------------------------------------
__global__ void detect_batch_kernel(const int* __restrict__ batch_i32, int n)
{
    g_batch_is_i32 = (batch_i32[n - 1] != 0) ? 1 : 0;
}

// ---------------------------------------------------------------------------
// Kernel 0b: segment offsets via binary search over sorted batch ids
// ---------------------------------------------------------------------------
__global__ void seg_offsets_kernel(const void* __restrict__ batch, int n, int Bseg)
{
    int b = blockIdx.x * blockDim.x + threadIdx.x;
    if (b > Bseg) return;
    const int i32 = g_batch_is_i32;
    int lo = 0, hi = n;
    if (i32) {
        const int* a = (const int*)batch;
        while (lo < hi) { int m = (lo + hi) >> 1; if (__ldg(a + m) < b) lo = m + 1; else hi = m; }
    } else {
        const long long* a = (const long long*)batch;
        while (lo < hi) { int m = (lo + hi) >> 1; if (__ldg(a + m) < (long long)b) lo = m + 1; else hi = m; }
    }
    g_off[b] = lo;
}

// ---------------------------------------------------------------------------
// Kernel 0c: split W1^T into bf16 hi/lo:  g_w1t_*[n*512 + k] = split(W1[k][n])
// ---------------------------------------------------------------------------
__global__ __launch_bounds__(256)
void w1_prep_kernel(const float* __restrict__ W1)
{
    int idx = blockIdx.x * blockDim.x + threadIdx.x;   // over 128*512
    if (idx >= HID * DIM) return;
    int nn = idx >> 9;         // 0..127
    int k  = idx & 511;        // 0..511
    float w = __ldg(W1 + (size_t)k * HID + nn);        // W1[k][n]
    __nv_bfloat16 hv = __float2bfloat16(w);
    __nv_bfloat16 lv = __float2bfloat16(w - __bfloat162float(hv));
    g_w1t_hi[idx] = __bfloat16_as_ushort(hv);
    g_w1t_lo[idx] = __bfloat16_as_ushort(lv);
}

// ---------------------------------------------------------------------------
// mma.sync m16n8k16 bf16 (sm_80+ baseline PTX -> works on compute_103)
// ---------------------------------------------------------------------------
__device__ __forceinline__ void mma_bf16(float* d, const uint32_t* a, const uint32_t* b)
{
    asm volatile(
        "mma.sync.aligned.m16n8k16.row.col.f32.bf16.bf16.f32 "
        "{%0,%1,%2,%3}, {%4,%5,%6,%7}, {%8,%9}, {%0,%1,%2,%3};"
        : "+f"(d[0]), "+f"(d[1]), "+f"(d[2]), "+f"(d[3])
        : "r"(a[0]), "r"(a[1]), "r"(a[2]), "r"(a[3]), "r"(b[0]), "r"(b[1]));
}

// ---------------------------------------------------------------------------
// Kernel 1: scores = tanh(x @ W1 + b1) @ W2 + b2  via split-bf16 mma.sync.
// Block: 128 rows x 128 cols (HID), 8 warps in 4x2 grid (warp tile 32x64).
// K loop: 8 tiles of 64. Smem rows padded to 72 elems (144B) -> fragment
// loads hit 32 distinct banks (bank = 4*grp + tig mod 32).
// ---------------------------------------------------------------------------
#define KT      64
#define ROWPAD  72                       // elements per smem row (144 bytes)
#define TILE_B  (128 * ROWPAD * 2)       // 18432 bytes per tile buffer
#define OFF_AHI 0
#define OFF_ALO (1 * TILE_B)
#define OFF_BHI (2 * TILE_B)
#define OFF_BLO (3 * TILE_B)
#define SMEM_REQ (4 * TILE_B)            // 73728 B

__global__ __launch_bounds__(256)
void score_mma_kernel(const float* __restrict__ x,
                      const float* __restrict__ b1,
                      const float* __restrict__ W2,
                      const float* __restrict__ b2)
{
    extern __shared__ char bp[];

    const int tid = threadIdx.x;
    const int wid = tid >> 5;
    const int lid = tid & 31;
    const int grp = lid >> 2;            // 0..7
    const int tig = lid & 3;             // 0..3
    const int warp_row = wid & 3;        // rows warp_row*32 ..
    const int warp_col = wid >> 2;       // cols warp_col*64 ..
    const int rowBase = blockIdx.x * 128;

    float acc[2][8][4];
#pragma unroll
    for (int m = 0; m < 2; m++)
#pragma unroll
        for (int nt = 0; nt < 8; nt++)
#pragma unroll
            for (int j = 0; j < 4; j++) acc[m][nt][j] = 0.f;

    for (int t = 0; t < 8; t++) {
        if (t > 0) __syncthreads();      // everyone done reading previous tile

        // --- stage A: x[rowBase..+127, t*64..+63] fp32 -> bf16 hi/lo (split)
#pragma unroll
        for (int u = 0; u < 4; u++) {
            int idx = tid + u * 256;     // 1024 chunks of 8 floats
            int r  = idx >> 3;
            int c8 = idx & 7;
            const float4* src = reinterpret_cast<const float4*>(
                x + (size_t)(rowBase + r) * DIM + t * KT + c8 * 8);
            float4 v0 = __ldg(src);
            float4 v1 = __ldg(src + 1);
            float f[8] = {v0.x, v0.y, v0.z, v0.w, v1.x, v1.y, v1.z, v1.w};
            uint32_t hp[4], lp[4];
#pragma unroll
            for (int j = 0; j < 4; j++) {
                __nv_bfloat16 h0 = __float2bfloat16(f[2 * j]);
                __nv_bfloat16 h1 = __float2bfloat16(f[2 * j + 1]);
                __nv_bfloat16 l0 = __float2bfloat16(f[2 * j]     - __bfloat162float(h0));
                __nv_bfloat16 l1 = __float2bfloat16(f[2 * j + 1] - __bfloat162float(h1));
                hp[j] = (uint32_t)__bfloat16_as_ushort(h0) | ((uint32_t)__bfloat16_as_ushort(h1) << 16);
                lp[j] = (uint32_t)__bfloat16_as_ushort(l0) | ((uint32_t)__bfloat16_as_ushort(l1) << 16);
            }
            uint32_t off = (uint32_t)r * (ROWPAD * 2) + (uint32_t)c8 * 16;
            *(uint4*)(bp + OFF_AHI + off) = make_uint4(hp[0], hp[1], hp[2], hp[3]);
            *(uint4*)(bp + OFF_ALO + off) = make_uint4(lp[0], lp[1], lp[2], lp[3]);
        }
        // --- stage B: W1t hi/lo [n][k] slices, 128 x 64 bf16 each
#pragma unroll
        for (int u = 0; u < 4; u++) {
            int idx = tid + u * 256;     // 1024 chunks of 8 bf16
            int nn = idx >> 3;
            int c8 = idx & 7;
            uint32_t goff = (uint32_t)nn * DIM + (uint32_t)t * KT + (uint32_t)c8 * 8;
            uint4 vh = __ldg(reinterpret_cast<const uint4*>(g_w1t_hi + goff));
            uint4 vl = __ldg(reinterpret_cast<const uint4*>(g_w1t_lo + goff));
            uint32_t off = (uint32_t)nn * (ROWPAD * 2) + (uint32_t)c8 * 16;
            *(uint4*)(bp + OFF_BHI + off) = vh;
            *(uint4*)(bp + OFF_BLO + off) = vl;
        }
        __syncthreads();

        // --- compute: 4 k-steps of 16
#pragma unroll
        for (int ks = 0; ks < 4; ks++) {
            const uint32_t kb = (uint32_t)(ks * 16 + tig * 2) * 2;   // byte offset of k pair
            uint32_t ah[2][4], al[2][4];
#pragma unroll
            for (int m = 0; m < 2; m++) {
                uint32_t r0 = (uint32_t)(warp_row * 32 + m * 16 + grp) * (ROWPAD * 2);
                ah[m][0] = *(const uint32_t*)(bp + OFF_AHI + r0 + kb);
                ah[m][1] = *(const uint32_t*)(bp + OFF_AHI + r0 + 8 * (ROWPAD * 2) + kb);
                ah[m][2] = *(const uint32_t*)(bp + OFF_AHI + r0 + kb + 16);
                ah[m][3] = *(const uint32_t*)(bp + OFF_AHI + r0 + 8 * (ROWPAD * 2) + kb + 16);
                al[m][0] = *(const uint32_t*)(bp + OFF_ALO + r0 + kb);
                al[m][1] = *(const uint32_t*)(bp + OFF_ALO + r0 + 8 * (ROWPAD * 2) + kb);
                al[m][2] = *(const uint32_t*)(bp + OFF_ALO + r0 + kb + 16);
                al[m][3] = *(const uint32_t*)(bp + OFF_ALO + r0 + 8 * (ROWPAD * 2) + kb + 16);
            }
#pragma unroll
            for (int nt = 0; nt < 8; nt++) {
                uint32_t n0 = (uint32_t)(warp_col * 64 + nt * 8 + grp) * (ROWPAD * 2);
                uint32_t bh[2], bl[2];
                bh[0] = *(const uint32_t*)(bp + OFF_BHI + n0 + kb);
                bh[1] = *(const uint32_t*)(bp + OFF_BHI + n0 + kb + 16);
                bl[0] = *(const uint32_t*)(bp + OFF_BLO + n0 + kb);
                bl[1] = *(const uint32_t*)(bp + OFF_BLO + n0 + kb + 16);
#pragma unroll
                for (int m = 0; m < 2; m++) {
                    mma_bf16(acc[m][nt], ah[m], bh);
                    mma_bf16(acc[m][nt], ah[m], bl);
                    mma_bf16(acc[m][nt], al[m], bh);
                }
            }
        }
    }

    // --- epilogue: s = sum_col tanh(h + b1[col]) * W2[col], register-resident
    float p[2][2] = {{0.f, 0.f}, {0.f, 0.f}};
#pragma unroll
    for (int nt = 0; nt < 8; nt++) {
        int c0 = warp_col * 64 + nt * 8 + tig * 2;
        float b1a = __ldg(b1 + c0),     b1b = __ldg(b1 + c0 + 1);
        float w2a = __ldg(W2 + c0),     w2b = __ldg(W2 + c0 + 1);
#pragma unroll
        for (int m = 0; m < 2; m++) {
            p[m][0] += tanhf(acc[m][nt][0] + b1a) * w2a + tanhf(acc[m][nt][1] + b1b) * w2b;
            p[m][1] += tanhf(acc[m][nt][2] + b1a) * w2a + tanhf(acc[m][nt][3] + b1b) * w2b;
        }
    }
    // reduce over the 4 lanes of each quad (cols)
#pragma unroll
    for (int m = 0; m < 2; m++)
#pragma unroll
        for (int r = 0; r < 2; r++) {
            p[m][r] += __shfl_xor_sync(0xFFFFFFFF, p[m][r], 1);
            p[m][r] += __shfl_xor_sync(0xFFFFFFFF, p[m][r], 2);
        }

    __syncthreads();                     // tiles no longer needed; reuse smem
    float* red = (float*)bp;             // [128][2]
    if (tig == 0) {
#pragma unroll
        for (int m = 0; m < 2; m++)
#pragma unroll
            for (int r = 0; r < 2; r++) {
                int row = warp_row * 32 + m * 16 + r * 8 + grp;
                red[row * 2 + warp_col] = p[m][r];
            }
    }
    __syncthreads();
    if (tid < 128)
        g_scores[rowBase + tid] = red[tid * 2] + red[tid * 2 + 1] + __ldg(b2);
}

// ---------------------------------------------------------------------------
// Kernel 2: per-segment softmax weights -> g_w
// (Per-segment max-shift == reference's global max-shift: shift-invariant;
//  the +1e-8 denom term contributes ~1e-9 relative.)
// ---------------------------------------------------------------------------
__global__ __launch_bounds__(256)
void seg_softmax_kernel()
{
    const int b = blockIdx.x;
    const int tid = threadIdx.x;
    __shared__ float red[256];

    const int lo = g_off[b];
    const int hi = g_off[b + 1];

    float m = -3.402823466e38f;
    for (int i = lo + tid; i < hi; i += 256) m = fmaxf(m, g_scores[i]);
    red[tid] = m;
    __syncthreads();
    for (int s = 128; s > 0; s >>= 1) {
        if (tid < s) red[tid] = fmaxf(red[tid], red[tid + s]);
        __syncthreads();
    }
    const float mm = red[0];
    __syncthreads();

    float sum = 0.f;
    for (int i = lo + tid; i < hi; i += 256) {
        float e = expf(g_scores[i] - mm);
        g_w[i] = e;
        sum += e;
    }
    red[tid] = sum;
    __syncthreads();
    for (int s = 128; s > 0; s >>= 1) {
        if (tid < s) red[tid] += red[tid + s];
        __syncthreads();
    }
    const float inv = 1.f / (red[0] + 1e-8f);

    for (int i = lo + tid; i < hi; i += 256) g_w[i] *= inv;
}

// ---------------------------------------------------------------------------
// Kernel 3: out[b, :] = sum_i w_i * x[i, :]
// ---------------------------------------------------------------------------
__global__ __launch_bounds__(128)
void pool_kernel(const float* __restrict__ x, float* __restrict__ out)
{
    const int b = blockIdx.x;
    const int tid = threadIdx.x;

    const int lo = g_off[b];
    const int hi = g_off[b + 1];

    const float4* xv = reinterpret_cast<const float4*>(x) + tid;
    float4 acc = make_float4(0.f, 0.f, 0.f, 0.f);

    int i = lo;
    for (; i + 4 <= hi; i += 4) {
        float w0 = __ldg(g_w + i + 0), w1 = __ldg(g_w + i + 1);
        float w2 = __ldg(g_w + i + 2), w3 = __ldg(g_w + i + 3);
        float4 v0 = __ldg(xv + (size_t)(i + 0) * (DIM / 4));
        float4 v1 = __ldg(xv + (size_t)(i + 1) * (DIM / 4));
        float4 v2 = __ldg(xv + (size_t)(i + 2) * (DIM / 4));
        float4 v3 = __ldg(xv + (size_t)(i + 3) * (DIM / 4));
        acc.x += w0 * v0.x + w1 * v1.x + w2 * v2.x + w3 * v3.x;
        acc.y += w0 * v0.y + w1 * v1.y + w2 * v2.y + w3 * v3.y;
        acc.z += w0 * v0.z + w1 * v1.z + w2 * v2.z + w3 * v3.z;
        acc.w += w0 * v0.w + w1 * v1.w + w2 * v2.w + w3 * v3.w;
    }
    for (; i < hi; i++) {
        float w = __ldg(g_w + i);
        float4 v = __ldg(xv + (size_t)i * (DIM / 4));
        acc.x += w * v.x; acc.y += w * v.y; acc.z += w * v.z; acc.w += w * v.w;
    }

    reinterpret_cast<float4*>(out)[(size_t)b * (DIM / 4) + tid] = acc;
}

// ---------------------------------------------------------------------------
extern "C" void kernel_launch(void* const* d_in, const int* in_sizes, int n_in,
                              void* d_out, int out_size)
{
    const float* x     = (const float*)d_in[0];
    const void*  batch = (const void*)d_in[1];
    const float* W1    = (const float*)d_in[2];
    const float* b1    = (const float*)d_in[3];
    const float* W2    = (const float*)d_in[4];
    const float* b2    = (const float*)d_in[5];
    float*       out   = (float*)d_out;

    const int n = in_sizes[1];
    const int Bseg = out_size / DIM;

    static int smem_set = 0;
    if (!smem_set) {
        cudaFuncSetAttribute(score_mma_kernel,
                             cudaFuncAttributeMaxDynamicSharedMemorySize, SMEM_REQ);
        smem_set = 1;
    }

    detect_batch_kernel<<<1, 1>>>((const int*)batch, n);
    seg_offsets_kernel<<<(Bseg + 256) / 256, 256>>>(batch, n, Bseg);
    w1_prep_kernel<<<(HID * DIM + 255) / 256, 256>>>(W1);
    score_mma_kernel<<<n / 128, 256, SMEM_REQ>>>(x, b1, W2, b2);
    seg_softmax_kernel<<<Bseg, 256>>>();
    pool_kernel<<<Bseg, 128>>>(x, out);
}

// round 5
// speedup vs baseline: 3.3729x; 1.1341x over previous
#include <cuda_runtime.h>
#include <cuda_bf16.h>
#include <cstdint>

// Problem constants (AttentionPool: N=262144, D=512, H=128, B=1024)
#define MAXN 262144
#define MAXB 4096
#define DIM 512
#define HID 128

// ---------------------------------------------------------------------------
// Scratch (allocation-free rule: __device__ globals)
// ---------------------------------------------------------------------------
__device__ float g_scores[MAXN];
__device__ float g_w[MAXN];
__device__ int   g_off[MAXB + 1];
__device__ int   g_batch_is_i32;
// W1^T split into bf16 hi/lo, layout [n][k]: n=0..127 rows, k=0..511 contiguous
__device__ __align__(16) unsigned short g_w1t_hi[HID * DIM];
__device__ __align__(16) unsigned short g_w1t_lo[HID * DIM];

// ---------------------------------------------------------------------------
// Kernel 0: detect batch dtype. int32: last element = max id > 0.
// int64 LE: i32 word at index n-1 (odd) is a high word = 0.
// ---------------------------------------------------------------------------
__global__ void detect_batch_kernel(const int* __restrict__ batch_i32, int n)
{
    g_batch_is_i32 = (batch_i32[n - 1] != 0) ? 1 : 0;
}

// ---------------------------------------------------------------------------
// Kernel 0b: segment offsets via binary search over sorted batch ids
// ---------------------------------------------------------------------------
__global__ void seg_offsets_kernel(const void* __restrict__ batch, int n, int Bseg)
{
    int b = blockIdx.x * blockDim.x + threadIdx.x;
    if (b > Bseg) return;
    const int i32 = g_batch_is_i32;
    int lo = 0, hi = n;
    if (i32) {
        const int* a = (const int*)batch;
        while (lo < hi) { int m = (lo + hi) >> 1; if (__ldg(a + m) < b) lo = m + 1; else hi = m; }
    } else {
        const long long* a = (const long long*)batch;
        while (lo < hi) { int m = (lo + hi) >> 1; if (__ldg(a + m) < (long long)b) lo = m + 1; else hi = m; }
    }
    g_off[b] = lo;
}

// ---------------------------------------------------------------------------
// Kernel 0c: split W1^T into bf16 hi/lo:  g_w1t_*[n*512 + k] = split(W1[k][n])
// ---------------------------------------------------------------------------
__global__ __launch_bounds__(256)
void w1_prep_kernel(const float* __restrict__ W1)
{
    int idx = blockIdx.x * blockDim.x + threadIdx.x;   // over 128*512
    if (idx >= HID * DIM) return;
    int nn = idx >> 9;         // 0..127
    int k  = idx & 511;        // 0..511
    float w = __ldg(W1 + (size_t)k * HID + nn);        // W1[k][n]
    __nv_bfloat16 hv = __float2bfloat16(w);
    __nv_bfloat16 lv = __float2bfloat16(w - __bfloat162float(hv));
    g_w1t_hi[idx] = __bfloat16_as_ushort(hv);
    g_w1t_lo[idx] = __bfloat16_as_ushort(lv);
}

// ---------------------------------------------------------------------------
// PTX helpers (all sm_80+ baseline -> safe for compute_103 target)
// ---------------------------------------------------------------------------
__device__ __forceinline__ void mma_bf16(float* d, const uint32_t* a, const uint32_t* b)
{
    asm volatile(
        "mma.sync.aligned.m16n8k16.row.col.f32.bf16.bf16.f32 "
        "{%0,%1,%2,%3}, {%4,%5,%6,%7}, {%8,%9}, {%0,%1,%2,%3};"
        : "+f"(d[0]), "+f"(d[1]), "+f"(d[2]), "+f"(d[3])
        : "r"(a[0]), "r"(a[1]), "r"(a[2]), "r"(a[3]), "r"(b[0]), "r"(b[1]));
}
__device__ __forceinline__ void ldsm_x4(uint32_t* r, uint32_t addr)
{
    asm volatile("ldmatrix.sync.aligned.m8n8.x4.shared.b16 {%0,%1,%2,%3}, [%4];"
                 : "=r"(r[0]), "=r"(r[1]), "=r"(r[2]), "=r"(r[3]) : "r"(addr));
}
__device__ __forceinline__ void cp16(uint32_t dst, const void* src)
{
    asm volatile("cp.async.cg.shared.global [%0], [%1], 16;"
                 :: "r"(dst), "l"(src) : "memory");
}
__device__ __forceinline__ void cp_commit()
{
    asm volatile("cp.async.commit_group;" ::: "memory");
}
template <int N>
__device__ __forceinline__ void cp_wait()
{
    asm volatile("cp.async.wait_group %0;" :: "n"(N) : "memory");
}
__device__ __forceinline__ uint32_t smem_u32(const void* p)
{
    uint32_t a;
    asm("{ .reg .u64 t; cvta.to.shared.u64 t, %1; cvt.u32.u64 %0, t; }" : "=r"(a) : "l"(p));
    return a;
}

// ---------------------------------------------------------------------------
// Kernel 1: scores = tanh(x @ W1 + b1) @ W2 + b2  via split-bf16 mma.sync.
// Block: 128 rows x 128 cols (HID), 8 warps in 4x2 grid (warp tile 32x64).
// K loop: 8 tiles of 64. Rows padded to 144B -> conflict-free ldmatrix.
// B tiles double-buffered via cp.async; A staged with batched LDGs.
// ---------------------------------------------------------------------------
#define KT       64
#define ROWPADB  144                      // bytes per smem row
#define TILE_B   (128 * ROWPADB)          // 18432 bytes per tile buffer
#define OFF_AHI  0
#define OFF_ALO  (1 * TILE_B)
#define OFF_B0   (2 * TILE_B)             // [hi | lo]
#define OFF_B1   (4 * TILE_B)             // [hi | lo]
#define SMEM_REQ (6 * TILE_B)             // 110592 B

__global__ __launch_bounds__(256, 2)
void score_mma_kernel(const float* __restrict__ x,
                      const float* __restrict__ b1,
                      const float* __restrict__ W2,
                      const float* __restrict__ b2)
{
    extern __shared__ char bp[];
    const uint32_t sbase = smem_u32(bp);

    const int tid = threadIdx.x;
    const int wid = tid >> 5;
    const int lid = tid & 31;
    const int tig = lid & 3;             // 0..3
    const int warp_row = wid & 3;        // rows warp_row*32 ..
    const int warp_col = wid >> 2;       // cols warp_col*64 ..
    const int rowBase = blockIdx.x * 128;

    // ldmatrix per-lane address components
    const uint32_t a_rl    = (uint32_t)(lid & 15);
    const uint32_t a_chalf = (uint32_t)((lid >> 4) * 16);
    uint32_t aHi[2], aLo[2];
#pragma unroll
    for (int m = 0; m < 2; m++) {
        uint32_t row = (uint32_t)(warp_row * 32 + m * 16) + a_rl;
        aHi[m] = sbase + OFF_AHI + row * ROWPADB + a_chalf;
        aLo[m] = sbase + OFF_ALO + row * ROWPADB + a_chalf;
    }
    const uint32_t b_lane = ((uint32_t)(lid & 7) + (uint32_t)((lid >> 4) & 1) * 8) * ROWPADB
                          + (uint32_t)((lid >> 3) & 1) * 16
                          + (uint32_t)warp_col * 64 * ROWPADB;

    float acc[2][8][4];
#pragma unroll
    for (int m = 0; m < 2; m++)
#pragma unroll
        for (int nt = 0; nt < 8; nt++)
#pragma unroll
            for (int j = 0; j < 4; j++) acc[m][nt][j] = 0.f;

    // --- prologue: B[0] via cp.async into buffer 0
    {
#pragma unroll
        for (int u = 0; u < 4; u++) {
            int idx = tid + u * 256;      // 1024 chunks of 16B per half
            int nn = idx >> 3, c8 = idx & 7;
            uint32_t doff = (uint32_t)nn * ROWPADB + (uint32_t)c8 * 16;
            uint32_t goff = (uint32_t)nn * DIM + (uint32_t)c8 * 8;  // t=0
            cp16(sbase + OFF_B0 + doff,          g_w1t_hi + goff);
            cp16(sbase + OFF_B0 + TILE_B + doff, g_w1t_lo + goff);
        }
        cp_commit();
    }

    for (int t = 0; t < 8; t++) {
        if (t > 0) __syncthreads();      // prior tile reads done before overwrite

        // --- stage A: batched LDGs, then convert fp32 -> bf16 hi/lo, then STS
        float4 va[8];
#pragma unroll
        for (int u = 0; u < 4; u++) {
            int idx = tid + u * 256;
            int r = idx >> 3, c8 = idx & 7;
            const float4* src = reinterpret_cast<const float4*>(
                x + (size_t)(rowBase + r) * DIM + t * KT + c8 * 8);
            va[2 * u]     = __ldg(src);
            va[2 * u + 1] = __ldg(src + 1);
        }
#pragma unroll
        for (int u = 0; u < 4; u++) {
            int idx = tid + u * 256;
            int r = idx >> 3, c8 = idx & 7;
            float f[8] = {va[2 * u].x, va[2 * u].y, va[2 * u].z, va[2 * u].w,
                          va[2 * u + 1].x, va[2 * u + 1].y, va[2 * u + 1].z, va[2 * u + 1].w};
            uint32_t hp[4], lp[4];
#pragma unroll
            for (int j = 0; j < 4; j++) {
                __nv_bfloat16 h0 = __float2bfloat16(f[2 * j]);
                __nv_bfloat16 h1 = __float2bfloat16(f[2 * j + 1]);
                __nv_bfloat16 l0 = __float2bfloat16(f[2 * j]     - __bfloat162float(h0));
                __nv_bfloat16 l1 = __float2bfloat16(f[2 * j + 1] - __bfloat162float(h1));
                hp[j] = (uint32_t)__bfloat16_as_ushort(h0) | ((uint32_t)__bfloat16_as_ushort(h1) << 16);
                lp[j] = (uint32_t)__bfloat16_as_ushort(l0) | ((uint32_t)__bfloat16_as_ushort(l1) << 16);
            }
            uint32_t off = (uint32_t)r * ROWPADB + (uint32_t)c8 * 16;
            *(uint4*)(bp + OFF_AHI + off) = make_uint4(hp[0], hp[1], hp[2], hp[3]);
            *(uint4*)(bp + OFF_ALO + off) = make_uint4(lp[0], lp[1], lp[2], lp[3]);
        }

        // --- issue B[t+1] cp.async into alternate buffer (overlaps compute)
        if (t < 7) {
            uint32_t bufo = ((t + 1) & 1) ? OFF_B1 : OFF_B0;
#pragma unroll
            for (int u = 0; u < 4; u++) {
                int idx = tid + u * 256;
                int nn = idx >> 3, c8 = idx & 7;
                uint32_t doff = (uint32_t)nn * ROWPADB + (uint32_t)c8 * 16;
                uint32_t goff = (uint32_t)nn * DIM + (uint32_t)(t + 1) * KT + (uint32_t)c8 * 8;
                cp16(sbase + bufo + doff,          g_w1t_hi + goff);
                cp16(sbase + bufo + TILE_B + doff, g_w1t_lo + goff);
            }
            cp_commit();
            cp_wait<1>();                 // B[t] complete; B[t+1] may stay in flight
        } else {
            cp_wait<0>();
        }
        __syncthreads();

        // --- compute: 4 k-steps of 16
        const uint32_t bHiA = sbase + ((t & 1) ? OFF_B1 : OFF_B0) + b_lane;
        const uint32_t bLoA = bHiA + TILE_B;
#pragma unroll
        for (int ks = 0; ks < 4; ks++) {
            const uint32_t ko = (uint32_t)ks * 32;
            uint32_t ah[2][4], al[2][4];
#pragma unroll
            for (int m = 0; m < 2; m++) {
                ldsm_x4(ah[m], aHi[m] + ko);
                ldsm_x4(al[m], aLo[m] + ko);
            }
#pragma unroll
            for (int ntp = 0; ntp < 4; ntp++) {
                const uint32_t no = (uint32_t)ntp * 16 * ROWPADB + ko;
                uint32_t bh[4], bl[4];
                ldsm_x4(bh, bHiA + no);
                ldsm_x4(bl, bLoA + no);
#pragma unroll
                for (int m = 0; m < 2; m++) {
                    mma_bf16(acc[m][2 * ntp],     ah[m], bh);
                    mma_bf16(acc[m][2 * ntp],     ah[m], bl);
                    mma_bf16(acc[m][2 * ntp],     al[m], bh);
                    mma_bf16(acc[m][2 * ntp + 1], ah[m], bh + 2);
                    mma_bf16(acc[m][2 * ntp + 1], ah[m], bl + 2);
                    mma_bf16(acc[m][2 * ntp + 1], al[m], bh + 2);
                }
            }
        }
    }

    // --- epilogue: s = sum_col tanh(h + b1[col]) * W2[col], register-resident
    const int grp = lid >> 2;
    float p[2][2] = {{0.f, 0.f}, {0.f, 0.f}};
#pragma unroll
    for (int nt = 0; nt < 8; nt++) {
        int c0 = warp_col * 64 + nt * 8 + tig * 2;
        float b1a = __ldg(b1 + c0),     b1b = __ldg(b1 + c0 + 1);
        float w2a = __ldg(W2 + c0),     w2b = __ldg(W2 + c0 + 1);
#pragma unroll
        for (int m = 0; m < 2; m++) {
            p[m][0] += tanhf(acc[m][nt][0] + b1a) * w2a + tanhf(acc[m][nt][1] + b1b) * w2b;
            p[m][1] += tanhf(acc[m][nt][2] + b1a) * w2a + tanhf(acc[m][nt][3] + b1b) * w2b;
        }
    }
#pragma unroll
    for (int m = 0; m < 2; m++)
#pragma unroll
        for (int r = 0; r < 2; r++) {
            p[m][r] += __shfl_xor_sync(0xFFFFFFFF, p[m][r], 1);
            p[m][r] += __shfl_xor_sync(0xFFFFFFFF, p[m][r], 2);
        }

    __syncthreads();                     // tiles no longer needed; reuse smem
    float* red = (float*)bp;             // [128][2]
    if (tig == 0) {
#pragma unroll
        for (int m = 0; m < 2; m++)
#pragma unroll
            for (int r = 0; r < 2; r++) {
                int row = warp_row * 32 + m * 16 + r * 8 + grp;
                red[row * 2 + warp_col] = p[m][r];
            }
    }
    __syncthreads();
    if (tid < 128)
        g_scores[rowBase + tid] = red[tid * 2] + red[tid * 2 + 1] + __ldg(b2);
}

// ---------------------------------------------------------------------------
// Kernel 2: per-segment softmax weights -> g_w
// (Per-segment max-shift == reference's global max-shift: shift-invariant;
//  the +1e-8 denom term contributes ~1e-9 relative.)
// ---------------------------------------------------------------------------
__global__ __launch_bounds__(256)
void seg_softmax_kernel()
{
    const int b = blockIdx.x;
    const int tid = threadIdx.x;
    __shared__ float red[256];

    const int lo = g_off[b];
    const int hi = g_off[b + 1];

    float m = -3.402823466e38f;
    for (int i = lo + tid; i < hi; i += 256) m = fmaxf(m, g_scores[i]);
    red[tid] = m;
    __syncthreads();
    for (int s = 128; s > 0; s >>= 1) {
        if (tid < s) red[tid] = fmaxf(red[tid], red[tid + s]);
        __syncthreads();
    }
    const float mm = red[0];
    __syncthreads();

    float sum = 0.f;
    for (int i = lo + tid; i < hi; i += 256) {
        float e = expf(g_scores[i] - mm);
        g_w[i] = e;
        sum += e;
    }
    red[tid] = sum;
    __syncthreads();
    for (int s = 128; s > 0; s >>= 1) {
        if (tid < s) red[tid] += red[tid + s];
        __syncthreads();
    }
    const float inv = 1.f / (red[0] + 1e-8f);

    for (int i = lo + tid; i < hi; i += 256) g_w[i] *= inv;
}

// ---------------------------------------------------------------------------
// Kernel 3: out[b, :] = sum_i w_i * x[i, :]
// ---------------------------------------------------------------------------
__global__ __launch_bounds__(128)
void pool_kernel(const float* __restrict__ x, float* __restrict__ out)
{
    const int b = blockIdx.x;
    const int tid = threadIdx.x;

    const int lo = g_off[b];
    const int hi = g_off[b + 1];

    const float4* xv = reinterpret_cast<const float4*>(x) + tid;
    float4 acc = make_float4(0.f, 0.f, 0.f, 0.f);

    int i = lo;
    for (; i + 4 <= hi; i += 4) {
        float w0 = __ldg(g_w + i + 0), w1 = __ldg(g_w + i + 1);
        float w2 = __ldg(g_w + i + 2), w3 = __ldg(g_w + i + 3);
        float4 v0 = __ldg(xv + (size_t)(i + 0) * (DIM / 4));
        float4 v1 = __ldg(xv + (size_t)(i + 1) * (DIM / 4));
        float4 v2 = __ldg(xv + (size_t)(i + 2) * (DIM / 4));
        float4 v3 = __ldg(xv + (size_t)(i + 3) * (DIM / 4));
        acc.x += w0 * v0.x + w1 * v1.x + w2 * v2.x + w3 * v3.x;
        acc.y += w0 * v0.y + w1 * v1.y + w2 * v2.y + w3 * v3.y;
        acc.z += w0 * v0.z + w1 * v1.z + w2 * v2.z + w3 * v3.z;
        acc.w += w0 * v0.w + w1 * v1.w + w2 * v2.w + w3 * v3.w;
    }
    for (; i < hi; i++) {
        float w = __ldg(g_w + i);
        float4 v = __ldg(xv + (size_t)i * (DIM / 4));
        acc.x += w * v.x; acc.y += w * v.y; acc.z += w * v.z; acc.w += w * v.w;
    }

    reinterpret_cast<float4*>(out)[(size_t)b * (DIM / 4) + tid] = acc;
}

// ---------------------------------------------------------------------------
extern "C" void kernel_launch(void* const* d_in, const int* in_sizes, int n_in,
                              void* d_out, int out_size)
{
    const float* x     = (const float*)d_in[0];
    const void*  batch = (const void*)d_in[1];
    const float* W1    = (const float*)d_in[2];
    const float* b1    = (const float*)d_in[3];
    const float* W2    = (const float*)d_in[4];
    const float* b2    = (const float*)d_in[5];
    float*       out   = (float*)d_out;

    const int n = in_sizes[1];
    const int Bseg = out_size / DIM;

    cudaFuncSetAttribute(score_mma_kernel,
                         cudaFuncAttributeMaxDynamicSharedMemorySize, SMEM_REQ);

    detect_batch_kernel<<<1, 1>>>((const int*)batch, n);
    seg_offsets_kernel<<<(Bseg + 256) / 256, 256>>>(batch, n, Bseg);
    w1_prep_kernel<<<(HID * DIM + 255) / 256, 256>>>(W1);
    score_mma_kernel<<<n / 128, 256, SMEM_REQ>>>(x, b1, W2, b2);
    seg_softmax_kernel<<<Bseg, 256>>>();
    pool_kernel<<<Bseg, 128>>>(x, out);
}

// round 6
// speedup vs baseline: 4.1140x; 1.2197x over previous
#include <cuda_runtime.h>
#include <cuda_bf16.h>
#include <cuda_fp16.h>
#include <cstdint>

// Problem constants (AttentionPool: N=262144, D=512, H=128, B=1024)
#define MAXN 262144
#define MAXB 4096
#define DIM 512
#define HID 128

// ---------------------------------------------------------------------------
// Scratch (allocation-free rule: __device__ globals)
// ---------------------------------------------------------------------------
__device__ float g_scores[MAXN];
__device__ float g_w[MAXN];
__device__ int   g_off[MAXB + 1];
__device__ int   g_batch_is_i32;
// W1^T split into fp16 hi/lo, layout [n][k]: n=0..127 rows, k=0..511 contiguous
__device__ __align__(16) unsigned short g_w1t_hi[HID * DIM];
__device__ __align__(16) unsigned short g_w1t_lo[HID * DIM];

// ---------------------------------------------------------------------------
// Kernel 0: detect batch dtype. int32: last element = max id > 0.
// int64 LE: i32 word at index n-1 (odd) is a high word = 0.
// ---------------------------------------------------------------------------
__global__ void detect_batch_kernel(const int* __restrict__ batch_i32, int n)
{
    g_batch_is_i32 = (batch_i32[n - 1] != 0) ? 1 : 0;
}

// ---------------------------------------------------------------------------
// Kernel 0b: segment offsets via binary search over sorted batch ids
// ---------------------------------------------------------------------------
__global__ void seg_offsets_kernel(const void* __restrict__ batch, int n, int Bseg)
{
    int b = blockIdx.x * blockDim.x + threadIdx.x;
    if (b > Bseg) return;
    const int i32 = g_batch_is_i32;
    int lo = 0, hi = n;
    if (i32) {
        const int* a = (const int*)batch;
        while (lo < hi) { int m = (lo + hi) >> 1; if (__ldg(a + m) < b) lo = m + 1; else hi = m; }
    } else {
        const long long* a = (const long long*)batch;
        while (lo < hi) { int m = (lo + hi) >> 1; if (__ldg(a + m) < (long long)b) lo = m + 1; else hi = m; }
    }
    g_off[b] = lo;
}

// ---------------------------------------------------------------------------
// Kernel 0c: split W1^T into fp16 hi/lo:  g_w1t_*[n*512 + k] = split(W1[k][n])
// ---------------------------------------------------------------------------
__global__ __launch_bounds__(256)
void w1_prep_kernel(const float* __restrict__ W1)
{
    int idx = blockIdx.x * blockDim.x + threadIdx.x;   // over 128*512
    if (idx >= HID * DIM) return;
    int nn = idx >> 9;         // 0..127
    int k  = idx & 511;        // 0..511
    float w = __ldg(W1 + (size_t)k * HID + nn);        // W1[k][n]
    __half hv = __float2half_rn(w);
    __half lv = __float2half_rn(w - __half2float(hv));
    g_w1t_hi[idx] = __half_as_ushort(hv);
    g_w1t_lo[idx] = __half_as_ushort(lv);
}

// ---------------------------------------------------------------------------
// PTX helpers (all sm_80+ baseline -> safe for compute_103 target)
// ---------------------------------------------------------------------------
__device__ __forceinline__ void mma_f16(float* d, const uint32_t* a, const uint32_t* b)
{
    asm volatile(
        "mma.sync.aligned.m16n8k16.row.col.f32.f16.f16.f32 "
        "{%0,%1,%2,%3}, {%4,%5,%6,%7}, {%8,%9}, {%0,%1,%2,%3};"
        : "+f"(d[0]), "+f"(d[1]), "+f"(d[2]), "+f"(d[3])
        : "r"(a[0]), "r"(a[1]), "r"(a[2]), "r"(a[3]), "r"(b[0]), "r"(b[1]));
}
__device__ __forceinline__ void ldsm_x4(uint32_t* r, uint32_t addr)
{
    asm volatile("ldmatrix.sync.aligned.m8n8.x4.shared.b16 {%0,%1,%2,%3}, [%4];"
                 : "=r"(r[0]), "=r"(r[1]), "=r"(r[2]), "=r"(r[3]) : "r"(addr));
}
__device__ __forceinline__ void cp16(uint32_t dst, const void* src)
{
    asm volatile("cp.async.cg.shared.global [%0], [%1], 16;"
                 :: "r"(dst), "l"(src) : "memory");
}
__device__ __forceinline__ void cp_commit()
{
    asm volatile("cp.async.commit_group;" ::: "memory");
}
template <int N>
__device__ __forceinline__ void cp_wait()
{
    asm volatile("cp.async.wait_group %0;" :: "n"(N) : "memory");
}
__device__ __forceinline__ uint32_t smem_u32(const void* p)
{
    uint32_t a;
    asm("{ .reg .u64 t; cvta.to.shared.u64 t, %1; cvt.u32.u64 %0, t; }" : "=r"(a) : "l"(p));
    return a;
}

// ---------------------------------------------------------------------------
// Kernel 1: scores = tanh(x @ W1 + b1) @ W2 + b2  via 2-pass fp16 mma.sync:
//   h = x_f16 @ W1hi + x_f16 @ W1lo   (W1 split fp16 hi/lo, fp32 accum)
// Block: 128 rows x 128 cols (HID), 8 warps in 4x2 grid (warp tile 32x64).
// K loop: 8 tiles of 64. Rows padded to 144B -> conflict-free ldmatrix.
// B double-buffered via cp.async; next A tile LDGs issued before compute.
// ---------------------------------------------------------------------------
#define KT       64
#define ROWPADB  144                      // bytes per smem row
#define TILE_B   (128 * ROWPADB)          // 18432 bytes per tile buffer
#define OFF_A    0
#define OFF_B0   (1 * TILE_B)             // [hi | lo]
#define OFF_B1   (3 * TILE_B)             // [hi | lo]
#define SMEM_REQ (5 * TILE_B)             // 92160 B

__global__ __launch_bounds__(256, 2)
void score_mma_kernel(const float* __restrict__ x,
                      const float* __restrict__ b1,
                      const float* __restrict__ W2,
                      const float* __restrict__ b2)
{
    extern __shared__ char bp[];
    const uint32_t sbase = smem_u32(bp);

    const int tid = threadIdx.x;
    const int wid = tid >> 5;
    const int lid = tid & 31;
    const int tig = lid & 3;             // 0..3
    const int warp_row = wid & 3;        // rows warp_row*32 ..
    const int warp_col = wid >> 2;       // cols warp_col*64 ..
    const int rowBase = blockIdx.x * 128;

    // ldmatrix per-lane addresses
    const uint32_t a_rl    = (uint32_t)(lid & 15);
    const uint32_t a_chalf = (uint32_t)((lid >> 4) * 16);
    uint32_t aA[2];
#pragma unroll
    for (int m = 0; m < 2; m++) {
        uint32_t row = (uint32_t)(warp_row * 32 + m * 16) + a_rl;
        aA[m] = sbase + OFF_A + row * ROWPADB + a_chalf;
    }
    const uint32_t b_lane = ((uint32_t)(lid & 7) + (uint32_t)((lid >> 4) & 1) * 8) * ROWPADB
                          + (uint32_t)((lid >> 3) & 1) * 16
                          + (uint32_t)warp_col * 64 * ROWPADB;

    float acc[2][8][4];
#pragma unroll
    for (int m = 0; m < 2; m++)
#pragma unroll
        for (int nt = 0; nt < 8; nt++)
#pragma unroll
            for (int j = 0; j < 4; j++) acc[m][nt][j] = 0.f;

    // staging indices for this thread (1024 16B-chunks per tile, 4 per thread)
    // chunk idx = tid + u*256 -> row = idx>>3, c8 = idx&7
    // --- prologue: B[0] via cp.async; A[0] LDGs into registers
    {
#pragma unroll
        for (int u = 0; u < 4; u++) {
            int idx = tid + u * 256;
            int nn = idx >> 3, c8 = idx & 7;
            uint32_t doff = (uint32_t)nn * ROWPADB + (uint32_t)c8 * 16;
            uint32_t goff = (uint32_t)nn * DIM + (uint32_t)c8 * 8;  // t=0
            cp16(sbase + OFF_B0 + doff,          g_w1t_hi + goff);
            cp16(sbase + OFF_B0 + TILE_B + doff, g_w1t_lo + goff);
        }
        cp_commit();
    }
    float4 va[8];
#pragma unroll
    for (int u = 0; u < 4; u++) {
        int idx = tid + u * 256;
        int r = idx >> 3, c8 = idx & 7;
        const float4* src = reinterpret_cast<const float4*>(
            x + (size_t)(rowBase + r) * DIM + c8 * 8);
        va[2 * u]     = __ldg(src);
        va[2 * u + 1] = __ldg(src + 1);
    }

    for (int t = 0; t < 8; t++) {
        if (t > 0) __syncthreads();      // prior tile reads done before overwrite

        // --- convert prefetched A (fp32 -> fp16) and store to smem
#pragma unroll
        for (int u = 0; u < 4; u++) {
            int idx = tid + u * 256;
            int r = idx >> 3, c8 = idx & 7;
            float f[8] = {va[2 * u].x, va[2 * u].y, va[2 * u].z, va[2 * u].w,
                          va[2 * u + 1].x, va[2 * u + 1].y, va[2 * u + 1].z, va[2 * u + 1].w};
            uint32_t hp[4];
#pragma unroll
            for (int j = 0; j < 4; j++) {
                __half h0 = __float2half_rn(f[2 * j]);
                __half h1 = __float2half_rn(f[2 * j + 1]);
                hp[j] = (uint32_t)__half_as_ushort(h0) | ((uint32_t)__half_as_ushort(h1) << 16);
            }
            uint32_t off = (uint32_t)r * ROWPADB + (uint32_t)c8 * 16;
            *(uint4*)(bp + OFF_A + off) = make_uint4(hp[0], hp[1], hp[2], hp[3]);
        }

        // --- issue B[t+1] cp.async into alternate buffer (overlaps compute)
        if (t < 7) {
            uint32_t bufo = ((t + 1) & 1) ? OFF_B1 : OFF_B0;
#pragma unroll
            for (int u = 0; u < 4; u++) {
                int idx = tid + u * 256;
                int nn = idx >> 3, c8 = idx & 7;
                uint32_t doff = (uint32_t)nn * ROWPADB + (uint32_t)c8 * 16;
                uint32_t goff = (uint32_t)nn * DIM + (uint32_t)(t + 1) * KT + (uint32_t)c8 * 8;
                cp16(sbase + bufo + doff,          g_w1t_hi + goff);
                cp16(sbase + bufo + TILE_B + doff, g_w1t_lo + goff);
            }
            cp_commit();
            cp_wait<1>();                 // B[t] complete; B[t+1] may stay in flight
        } else {
            cp_wait<0>();
        }
        __syncthreads();

        // --- prefetch next A tile LDGs (latency hidden behind compute below)
        if (t < 7) {
#pragma unroll
            for (int u = 0; u < 4; u++) {
                int idx = tid + u * 256;
                int r = idx >> 3, c8 = idx & 7;
                const float4* src = reinterpret_cast<const float4*>(
                    x + (size_t)(rowBase + r) * DIM + (t + 1) * KT + c8 * 8);
                va[2 * u]     = __ldg(src);
                va[2 * u + 1] = __ldg(src + 1);
            }
        }

        // --- compute: 4 k-steps of 16, 2 passes (W hi + W lo)
        const uint32_t bHiA = sbase + ((t & 1) ? OFF_B1 : OFF_B0) + b_lane;
        const uint32_t bLoA = bHiA + TILE_B;
#pragma unroll
        for (int ks = 0; ks < 4; ks++) {
            const uint32_t ko = (uint32_t)ks * 32;
            uint32_t a[2][4];
#pragma unroll
            for (int m = 0; m < 2; m++) ldsm_x4(a[m], aA[m] + ko);
#pragma unroll
            for (int ntp = 0; ntp < 4; ntp++) {
                const uint32_t no = (uint32_t)ntp * 16 * ROWPADB + ko;
                uint32_t bh[4], bl[4];
                ldsm_x4(bh, bHiA + no);
                ldsm_x4(bl, bLoA + no);
#pragma unroll
                for (int m = 0; m < 2; m++) {
                    mma_f16(acc[m][2 * ntp],     a[m], bh);
                    mma_f16(acc[m][2 * ntp],     a[m], bl);
                    mma_f16(acc[m][2 * ntp + 1], a[m], bh + 2);
                    mma_f16(acc[m][2 * ntp + 1], a[m], bl + 2);
                }
            }
        }
    }

    // --- epilogue: s = sum_col tanh(h + b1[col]) * W2[col], register-resident
    const int grp = lid >> 2;
    float p[2][2] = {{0.f, 0.f}, {0.f, 0.f}};
#pragma unroll
    for (int nt = 0; nt < 8; nt++) {
        int c0 = warp_col * 64 + nt * 8 + tig * 2;
        float b1a = __ldg(b1 + c0),     b1b = __ldg(b1 + c0 + 1);
        float w2a = __ldg(W2 + c0),     w2b = __ldg(W2 + c0 + 1);
#pragma unroll
        for (int m = 0; m < 2; m++) {
            p[m][0] += tanhf(acc[m][nt][0] + b1a) * w2a + tanhf(acc[m][nt][1] + b1b) * w2b;
            p[m][1] += tanhf(acc[m][nt][2] + b1a) * w2a + tanhf(acc[m][nt][3] + b1b) * w2b;
        }
    }
#pragma unroll
    for (int m = 0; m < 2; m++)
#pragma unroll
        for (int r = 0; r < 2; r++) {
            p[m][r] += __shfl_xor_sync(0xFFFFFFFF, p[m][r], 1);
            p[m][r] += __shfl_xor_sync(0xFFFFFFFF, p[m][r], 2);
        }

    __syncthreads();                     // tiles no longer needed; reuse smem
    float* red = (float*)bp;             // [128][2]
    if (tig == 0) {
#pragma unroll
        for (int m = 0; m < 2; m++)
#pragma unroll
            for (int r = 0; r < 2; r++) {
                int row = warp_row * 32 + m * 16 + r * 8 + grp;
                red[row * 2 + warp_col] = p[m][r];
            }
    }
    __syncthreads();
    if (tid < 128)
        g_scores[rowBase + tid] = red[tid * 2] + red[tid * 2 + 1] + __ldg(b2);
}

// ---------------------------------------------------------------------------
// Kernel 2: per-segment softmax weights -> g_w
// (Per-segment max-shift == reference's global max-shift: shift-invariant;
//  the +1e-8 denom term contributes ~1e-9 relative.)
// ---------------------------------------------------------------------------
__global__ __launch_bounds__(256)
void seg_softmax_kernel()
{
    const int b = blockIdx.x;
    const int tid = threadIdx.x;
    __shared__ float red[256];

    const int lo = g_off[b];
    const int hi = g_off[b + 1];

    float m = -3.402823466e38f;
    for (int i = lo + tid; i < hi; i += 256) m = fmaxf(m, g_scores[i]);
    red[tid] = m;
    __syncthreads();
    for (int s = 128; s > 0; s >>= 1) {
        if (tid < s) red[tid] = fmaxf(red[tid], red[tid + s]);
        __syncthreads();
    }
    const float mm = red[0];
    __syncthreads();

    float sum = 0.f;
    for (int i = lo + tid; i < hi; i += 256) {
        float e = expf(g_scores[i] - mm);
        g_w[i] = e;
        sum += e;
    }
    red[tid] = sum;
    __syncthreads();
    for (int s = 128; s > 0; s >>= 1) {
        if (tid < s) red[tid] += red[tid + s];
        __syncthreads();
    }
    const float inv = 1.f / (red[0] + 1e-8f);

    for (int i = lo + tid; i < hi; i += 256) g_w[i] *= inv;
}

// ---------------------------------------------------------------------------
// Kernel 3: out[b, :] = sum_i w_i * x[i, :]
// 256 threads: two row-halves in parallel, combined via smem.
// ---------------------------------------------------------------------------
__global__ __launch_bounds__(256)
void pool_kernel(const float* __restrict__ x, float* __restrict__ out)
{
    const int b = blockIdx.x;
    const int tid = threadIdx.x;
    const int half = tid >> 7;           // 0/1
    const int t = tid & 127;             // column group (float4)
    __shared__ float4 sh[128];

    const int lo = g_off[b];
    const int hi = g_off[b + 1];
    const int mid = lo + ((hi - lo) >> 1);
    const int s0 = half ? mid : lo;
    const int e0 = half ? hi : mid;

    const float4* xv = reinterpret_cast<const float4*>(x) + t;
    float4 acc = make_float4(0.f, 0.f, 0.f, 0.f);

    int i = s0;
    for (; i + 4 <= e0; i += 4) {
        float w0 = __ldg(g_w + i + 0), w1 = __ldg(g_w + i + 1);
        float w2 = __ldg(g_w + i + 2), w3 = __ldg(g_w + i + 3);
        float4 v0 = __ldg(xv + (size_t)(i + 0) * (DIM / 4));
        float4 v1 = __ldg(xv + (size_t)(i + 1) * (DIM / 4));
        float4 v2 = __ldg(xv + (size_t)(i + 2) * (DIM / 4));
        float4 v3 = __ldg(xv + (size_t)(i + 3) * (DIM / 4));
        acc.x += w0 * v0.x + w1 * v1.x + w2 * v2.x + w3 * v3.x;
        acc.y += w0 * v0.y + w1 * v1.y + w2 * v2.y + w3 * v3.y;
        acc.z += w0 * v0.z + w1 * v1.z + w2 * v2.z + w3 * v3.z;
        acc.w += w0 * v0.w + w1 * v1.w + w2 * v2.w + w3 * v3.w;
    }
    for (; i < e0; i++) {
        float w = __ldg(g_w + i);
        float4 v = __ldg(xv + (size_t)i * (DIM / 4));
        acc.x += w * v.x; acc.y += w * v.y; acc.z += w * v.z; acc.w += w * v.w;
    }

    if (half) sh[t] = acc;
    __syncthreads();
    if (!half) {
        float4 o = sh[t];
        acc.x += o.x; acc.y += o.y; acc.z += o.z; acc.w += o.w;
        reinterpret_cast<float4*>(out)[(size_t)b * (DIM / 4) + t] = acc;
    }
}

// ---------------------------------------------------------------------------
extern "C" void kernel_launch(void* const* d_in, const int* in_sizes, int n_in,
                              void* d_out, int out_size)
{
    const float* x     = (const float*)d_in[0];
    const void*  batch = (const void*)d_in[1];
    const float* W1    = (const float*)d_in[2];
    const float* b1    = (const float*)d_in[3];
    const float* W2    = (const float*)d_in[4];
    const float* b2    = (const float*)d_in[5];
    float*       out   = (float*)d_out;

    const int n = in_sizes[1];
    const int Bseg = out_size / DIM;

    cudaFuncSetAttribute(score_mma_kernel,
                         cudaFuncAttributeMaxDynamicSharedMemorySize, SMEM_REQ);

    detect_batch_kernel<<<1, 1>>>((const int*)batch, n);
    seg_offsets_kernel<<<(Bseg + 256) / 256, 256>>>(batch, n, Bseg);
    w1_prep_kernel<<<(HID * DIM + 255) / 256, 256>>>(W1);
    score_mma_kernel<<<n / 128, 256, SMEM_REQ>>>(x, b1, W2, b2);
    seg_softmax_kernel<<<Bseg, 256>>>();
    pool_kernel<<<Bseg, 256>>>(x, out);
}

// round 8
// speedup vs baseline: 5.8822x; 1.4298x over previous
#include <cuda_runtime.h>
#include <cuda_bf16.h>
#include <cuda_fp16.h>
#include <cstdint>

// Problem constants (AttentionPool: N=262144, D=512, H=128, B=1024)
#define MAXN 262144
#define MAXB 4096
#define DIM 512
#define HID 128

// ---------------------------------------------------------------------------
// Scratch (allocation-free rule: __device__ globals)
// ---------------------------------------------------------------------------
__device__ float g_scores[MAXN];
__device__ float g_w[MAXN];
__device__ int   g_off[MAXB + 1];
__device__ int   g_batch_is_i32;
// W1^T as fp16, layout [n][k]: n=0..127 rows, k=0..511 contiguous
__device__ __align__(16) unsigned short g_w1t[HID * DIM];
// x converted to fp16 by score kernel, row-major [N][D] (256 MB)
__device__ __align__(16) unsigned short g_xf16[(size_t)MAXN * DIM];

// ---------------------------------------------------------------------------
// Kernel 0: detect batch dtype. int32: last element = max id > 0.
// int64 LE: i32 word at index n-1 (odd) is a high word = 0.
// ---------------------------------------------------------------------------
__global__ void detect_batch_kernel(const int* __restrict__ batch_i32, int n)
{
    g_batch_is_i32 = (batch_i32[n - 1] != 0) ? 1 : 0;
}

// ---------------------------------------------------------------------------
// Kernel 0b: segment offsets via binary search over sorted batch ids
// ---------------------------------------------------------------------------
__global__ void seg_offsets_kernel(const void* __restrict__ batch, int n, int Bseg)
{
    int b = blockIdx.x * blockDim.x + threadIdx.x;
    if (b > Bseg) return;
    const int i32 = g_batch_is_i32;
    int lo = 0, hi = n;
    if (i32) {
        const int* a = (const int*)batch;
        while (lo < hi) { int m = (lo + hi) >> 1; if (__ldg(a + m) < b) lo = m + 1; else hi = m; }
    } else {
        const long long* a = (const long long*)batch;
        while (lo < hi) { int m = (lo + hi) >> 1; if (__ldg(a + m) < (long long)b) lo = m + 1; else hi = m; }
    }
    g_off[b] = lo;
}

// ---------------------------------------------------------------------------
// Kernel 0c: W1^T fp16:  g_w1t[n*512 + k] = fp16(W1[k][n])
// ---------------------------------------------------------------------------
__global__ __launch_bounds__(256)
void w1_prep_kernel(const float* __restrict__ W1)
{
    int idx = blockIdx.x * blockDim.x + threadIdx.x;   // over 128*512
    if (idx >= HID * DIM) return;
    int nn = idx >> 9;         // 0..127
    int k  = idx & 511;        // 0..511
    float w = __ldg(W1 + (size_t)k * HID + nn);        // W1[k][n]
    g_w1t[idx] = __half_as_ushort(__float2half_rn(w));
}

// ---------------------------------------------------------------------------
// PTX helpers (all sm_80+ baseline -> safe for compute_103 target)
// ---------------------------------------------------------------------------
__device__ __forceinline__ void mma_f16(float* d, const uint32_t* a, const uint32_t* b)
{
    asm volatile(
        "mma.sync.aligned.m16n8k16.row.col.f32.f16.f16.f32 "
        "{%0,%1,%2,%3}, {%4,%5,%6,%7}, {%8,%9}, {%0,%1,%2,%3};"
        : "+f"(d[0]), "+f"(d[1]), "+f"(d[2]), "+f"(d[3])
        : "r"(a[0]), "r"(a[1]), "r"(a[2]), "r"(a[3]), "r"(b[0]), "r"(b[1]));
}
__device__ __forceinline__ void ldsm_x4(uint32_t* r, uint32_t addr)
{
    asm volatile("ldmatrix.sync.aligned.m8n8.x4.shared.b16 {%0,%1,%2,%3}, [%4];"
                 : "=r"(r[0]), "=r"(r[1]), "=r"(r[2]), "=r"(r[3]) : "r"(addr));
}
__device__ __forceinline__ void cp16(uint32_t dst, const void* src)
{
    asm volatile("cp.async.cg.shared.global [%0], [%1], 16;"
                 :: "r"(dst), "l"(src) : "memory");
}
__device__ __forceinline__ void cp_commit()
{
    asm volatile("cp.async.commit_group;" ::: "memory");
}
template <int N>
__device__ __forceinline__ void cp_wait()
{
    asm volatile("cp.async.wait_group %0;" :: "n"(N) : "memory");
}
__device__ __forceinline__ uint32_t smem_u32(const void* p)
{
    uint32_t a;
    asm("{ .reg .u64 t; cvta.to.shared.u64 t, %1; cvt.u32.u64 %0, t; }" : "=r"(a) : "l"(p));
    return a;
}

// ---------------------------------------------------------------------------
// Kernel 1: scores = tanh(x @ W1 + b1) @ W2 + b2  via single-pass fp16 mma.
// Side effect: writes x as fp16 to g_xf16 (consumed by pool_kernel).
// Block: 128 rows x 128 cols (HID), 8 warps in 4x2 grid (warp tile 32x64).
// K loop: 8 tiles of 64. Rows padded to 144B -> conflict-free ldmatrix.
// B double-buffered via cp.async; next A tile LDGs issued before compute.
// ---------------------------------------------------------------------------
#define KT       64
#define ROWPADB  144                      // bytes per smem row
#define TILE_B   (128 * ROWPADB)          // 18432 bytes per tile buffer
#define OFF_A    0
#define OFF_B0   (1 * TILE_B)
#define OFF_B1   (2 * TILE_B)
#define SMEM_REQ (3 * TILE_B)             // 55296 B

__global__ __launch_bounds__(256, 2)
void score_mma_kernel(const float* __restrict__ x,
                      const float* __restrict__ b1,
                      const float* __restrict__ W2,
                      const float* __restrict__ b2)
{
    extern __shared__ char bp[];
    const uint32_t sbase = smem_u32(bp);

    const int tid = threadIdx.x;
    const int wid = tid >> 5;
    const int lid = tid & 31;
    const int tig = lid & 3;             // 0..3
    const int warp_row = wid & 3;        // rows warp_row*32 ..
    const int warp_col = wid >> 2;       // cols warp_col*64 ..
    const int rowBase = blockIdx.x * 128;

    // ldmatrix per-lane addresses
    const uint32_t a_rl    = (uint32_t)(lid & 15);
    const uint32_t a_chalf = (uint32_t)((lid >> 4) * 16);
    uint32_t aA[2];
#pragma unroll
    for (int m = 0; m < 2; m++) {
        uint32_t row = (uint32_t)(warp_row * 32 + m * 16) + a_rl;
        aA[m] = sbase + OFF_A + row * ROWPADB + a_chalf;
    }
    const uint32_t b_lane = ((uint32_t)(lid & 7) + (uint32_t)((lid >> 4) & 1) * 8) * ROWPADB
                          + (uint32_t)((lid >> 3) & 1) * 16
                          + (uint32_t)warp_col * 64 * ROWPADB;

    float acc[2][8][4];
#pragma unroll
    for (int m = 0; m < 2; m++)
#pragma unroll
        for (int nt = 0; nt < 8; nt++)
#pragma unroll
            for (int j = 0; j < 4; j++) acc[m][nt][j] = 0.f;

    // --- prologue: B[0] via cp.async; A[0] LDGs into registers
    {
#pragma unroll
        for (int u = 0; u < 4; u++) {
            int idx = tid + u * 256;
            int nn = idx >> 3, c8 = idx & 7;
            uint32_t doff = (uint32_t)nn * ROWPADB + (uint32_t)c8 * 16;
            uint32_t goff = (uint32_t)nn * DIM + (uint32_t)c8 * 8;  // t=0
            cp16(sbase + OFF_B0 + doff, g_w1t + goff);
        }
        cp_commit();
    }
    float4 va[8];
#pragma unroll
    for (int u = 0; u < 4; u++) {
        int idx = tid + u * 256;
        int r = idx >> 3, c8 = idx & 7;
        const float4* src = reinterpret_cast<const float4*>(
            x + (size_t)(rowBase + r) * DIM + c8 * 8);
        va[2 * u]     = __ldg(src);
        va[2 * u + 1] = __ldg(src + 1);
    }

    for (int t = 0; t < 8; t++) {
        if (t > 0) __syncthreads();      // prior tile reads done before overwrite

        // --- convert prefetched A (fp32 -> fp16): store to smem + gmem side copy
#pragma unroll
        for (int u = 0; u < 4; u++) {
            int idx = tid + u * 256;
            int r = idx >> 3, c8 = idx & 7;
            float f[8] = {va[2 * u].x, va[2 * u].y, va[2 * u].z, va[2 * u].w,
                          va[2 * u + 1].x, va[2 * u + 1].y, va[2 * u + 1].z, va[2 * u + 1].w};
            uint32_t hp[4];
#pragma unroll
            for (int j = 0; j < 4; j++) {
                __half h0 = __float2half_rn(f[2 * j]);
                __half h1 = __float2half_rn(f[2 * j + 1]);
                hp[j] = (uint32_t)__half_as_ushort(h0) | ((uint32_t)__half_as_ushort(h1) << 16);
            }
            uint32_t off = (uint32_t)r * ROWPADB + (uint32_t)c8 * 16;
            uint4 v = make_uint4(hp[0], hp[1], hp[2], hp[3]);
            *(uint4*)(bp + OFF_A + off) = v;
            // side copy: x fp16 for pool_kernel ([row][k] row-major, 8 halfs/chunk)
            *reinterpret_cast<uint4*>(g_xf16 +
                (size_t)(rowBase + r) * DIM + t * KT + c8 * 8) = v;
        }

        // --- issue B[t+1] cp.async into alternate buffer (overlaps compute)
        if (t < 7) {
            uint32_t bufo = ((t + 1) & 1) ? OFF_B1 : OFF_B0;
#pragma unroll
            for (int u = 0; u < 4; u++) {
                int idx = tid + u * 256;
                int nn = idx >> 3, c8 = idx & 7;
                uint32_t doff = (uint32_t)nn * ROWPADB + (uint32_t)c8 * 16;
                uint32_t goff = (uint32_t)nn * DIM + (uint32_t)(t + 1) * KT + (uint32_t)c8 * 8;
                cp16(sbase + bufo + doff, g_w1t + goff);
            }
            cp_commit();
            cp_wait<1>();                 // B[t] complete; B[t+1] may stay in flight
        } else {
            cp_wait<0>();
        }
        __syncthreads();

        // --- prefetch next A tile LDGs (latency hidden behind compute below)
        if (t < 7) {
#pragma unroll
            for (int u = 0; u < 4; u++) {
                int idx = tid + u * 256;
                int r = idx >> 3, c8 = idx & 7;
                const float4* src = reinterpret_cast<const float4*>(
                    x + (size_t)(rowBase + r) * DIM + (t + 1) * KT + c8 * 8);
                va[2 * u]     = __ldg(src);
                va[2 * u + 1] = __ldg(src + 1);
            }
        }

        // --- compute: 4 k-steps of 16, single pass
        const uint32_t bA = sbase + ((t & 1) ? OFF_B1 : OFF_B0) + b_lane;
#pragma unroll
        for (int ks = 0; ks < 4; ks++) {
            const uint32_t ko = (uint32_t)ks * 32;
            uint32_t a[2][4];
#pragma unroll
            for (int m = 0; m < 2; m++) ldsm_x4(a[m], aA[m] + ko);
#pragma unroll
            for (int ntp = 0; ntp < 4; ntp++) {
                const uint32_t no = (uint32_t)ntp * 16 * ROWPADB + ko;
                uint32_t bh[4];
                ldsm_x4(bh, bA + no);
#pragma unroll
                for (int m = 0; m < 2; m++) {
                    mma_f16(acc[m][2 * ntp],     a[m], bh);
                    mma_f16(acc[m][2 * ntp + 1], a[m], bh + 2);
                }
            }
        }
    }

    // --- epilogue: s = sum_col tanh(h + b1[col]) * W2[col], register-resident
    const int grp = lid >> 2;
    float p[2][2] = {{0.f, 0.f}, {0.f, 0.f}};
#pragma unroll
    for (int nt = 0; nt < 8; nt++) {
        int c0 = warp_col * 64 + nt * 8 + tig * 2;
        float b1a = __ldg(b1 + c0),     b1b = __ldg(b1 + c0 + 1);
        float w2a = __ldg(W2 + c0),     w2b = __ldg(W2 + c0 + 1);
#pragma unroll
        for (int m = 0; m < 2; m++) {
            p[m][0] += tanhf(acc[m][nt][0] + b1a) * w2a + tanhf(acc[m][nt][1] + b1b) * w2b;
            p[m][1] += tanhf(acc[m][nt][2] + b1a) * w2a + tanhf(acc[m][nt][3] + b1b) * w2b;
        }
    }
#pragma unroll
    for (int m = 0; m < 2; m++)
#pragma unroll
        for (int r = 0; r < 2; r++) {
            p[m][r] += __shfl_xor_sync(0xFFFFFFFF, p[m][r], 1);
            p[m][r] += __shfl_xor_sync(0xFFFFFFFF, p[m][r], 2);
        }

    __syncthreads();                     // tiles no longer needed; reuse smem
    float* red = (float*)bp;             // [128][2]
    if (tig == 0) {
#pragma unroll
        for (int m = 0; m < 2; m++)
#pragma unroll
            for (int r = 0; r < 2; r++) {
                int row = warp_row * 32 + m * 16 + r * 8 + grp;
                red[row * 2 + warp_col] = p[m][r];
            }
    }
    __syncthreads();
    if (tid < 128)
        g_scores[rowBase + tid] = red[tid * 2] + red[tid * 2 + 1] + __ldg(b2);
}

// ---------------------------------------------------------------------------
// Kernel 2: per-segment softmax weights -> g_w
// (Per-segment max-shift == reference's global max-shift: shift-invariant;
//  the +1e-8 denom term contributes ~1e-9 relative.)
// ---------------------------------------------------------------------------
__global__ __launch_bounds__(256)
void seg_softmax_kernel()
{
    const int b = blockIdx.x;
    const int tid = threadIdx.x;
    __shared__ float red[256];

    const int lo = g_off[b];
    const int hi = g_off[b + 1];

    float m = -3.402823466e38f;
    for (int i = lo + tid; i < hi; i += 256) m = fmaxf(m, g_scores[i]);
    red[tid] = m;
    __syncthreads();
    for (int s = 128; s > 0; s >>= 1) {
        if (tid < s) red[tid] = fmaxf(red[tid], red[tid + s]);
        __syncthreads();
    }
    const float mm = red[0];
    __syncthreads();

    float sum = 0.f;
    for (int i = lo + tid; i < hi; i += 256) {
        float e = expf(g_scores[i] - mm);
        g_w[i] = e;
        sum += e;
    }
    red[tid] = sum;
    __syncthreads();
    for (int s = 128; s > 0; s >>= 1) {
        if (tid < s) red[tid] += red[tid + s];
        __syncthreads();
    }
    const float inv = 1.f / (red[0] + 1e-8f);

    for (int i = lo + tid; i < hi; i += 256) g_w[i] *= inv;
}

// ---------------------------------------------------------------------------
// Kernel 3: out[b, :] = sum_i w_i * x_f16[i, :]  (fp32 accumulate)
// 256 threads = 4 row-quarters (q = tid>>6) x 64 column-chunks (t = tid&63,
// 8 halfs = 16B each; 64 chunks cover D=512). Partials combined via smem.
// ---------------------------------------------------------------------------
__global__ __launch_bounds__(256)
void pool_kernel(float* __restrict__ out)
{
    const int b = blockIdx.x;
    const int tid = threadIdx.x;
    const int q = tid >> 6;              // 0..3 row quarter
    const int t = tid & 63;              // column chunk
    __shared__ float sh[3][64][8];       // partials from quarters 1..3

    const int lo = g_off[b];
    const int hi = g_off[b + 1];
    const int len = hi - lo;
    const int s0 = lo + (int)(((long long)len * q) >> 2);
    const int e0 = lo + (int)(((long long)len * (q + 1)) >> 2);

    const uint4* xv = reinterpret_cast<const uint4*>(g_xf16) + t;  // + i*64 per row
    float a[8];
#pragma unroll
    for (int j = 0; j < 8; j++) a[j] = 0.f;

    int i = s0;
    for (; i + 2 <= e0; i += 2) {
        float w0 = __ldg(g_w + i), w1 = __ldg(g_w + i + 1);
        uint4 v0 = __ldg(xv + (size_t)i * (DIM / 8));
        uint4 v1 = __ldg(xv + (size_t)(i + 1) * (DIM / 8));
        const uint32_t* u0 = &v0.x;
        const uint32_t* u1 = &v1.x;
#pragma unroll
        for (int j = 0; j < 4; j++) {
            float2 f0 = __half22float2(*reinterpret_cast<const __half2*>(&u0[j]));
            float2 f1 = __half22float2(*reinterpret_cast<const __half2*>(&u1[j]));
            a[2 * j]     += w0 * f0.x + w1 * f1.x;
            a[2 * j + 1] += w0 * f0.y + w1 * f1.y;
        }
    }
    for (; i < e0; i++) {
        float w = __ldg(g_w + i);
        uint4 v = __ldg(xv + (size_t)i * (DIM / 8));
        const uint32_t* u = &v.x;
#pragma unroll
        for (int j = 0; j < 4; j++) {
            float2 f = __half22float2(*reinterpret_cast<const __half2*>(&u[j]));
            a[2 * j]     += w * f.x;
            a[2 * j + 1] += w * f.y;
        }
    }

    if (q > 0) {
#pragma unroll
        for (int j = 0; j < 8; j++) sh[q - 1][t][j] = a[j];
    }
    __syncthreads();
    if (q == 0) {
#pragma unroll
        for (int j = 0; j < 8; j++)
            a[j] += sh[0][t][j] + sh[1][t][j] + sh[2][t][j];
        float4* o = reinterpret_cast<float4*>(out + (size_t)b * DIM + t * 8);
        o[0] = make_float4(a[0], a[1], a[2], a[3]);
        o[1] = make_float4(a[4], a[5], a[6], a[7]);
    }
}

// ---------------------------------------------------------------------------
extern "C" void kernel_launch(void* const* d_in, const int* in_sizes, int n_in,
                              void* d_out, int out_size)
{
    const float* x     = (const float*)d_in[0];
    const void*  batch = (const void*)d_in[1];
    const float* W1    = (const float*)d_in[2];
    const float* b1    = (const float*)d_in[3];
    const float* W2    = (const float*)d_in[4];
    const float* b2    = (const float*)d_in[5];
    float*       out   = (float*)d_out;

    const int n = in_sizes[1];
    const int Bseg = out_size / DIM;

    cudaFuncSetAttribute(score_mma_kernel,
                         cudaFuncAttributeMaxDynamicSharedMemorySize, SMEM_REQ);

    detect_batch_kernel<<<1, 1>>>((const int*)batch, n);
    seg_offsets_kernel<<<(Bseg + 256) / 256, 256>>>(batch, n, Bseg);
    w1_prep_kernel<<<(HID * DIM + 255) / 256, 256>>>(W1);
    score_mma_kernel<<<n / 128, 256, SMEM_REQ>>>(x, b1, W2, b2);
    seg_softmax_kernel<<<Bseg, 256>>>();
    pool_kernel<<<Bseg, 256>>>(out);
}